// round 13
// baseline (speedup 1.0000x reference)
#include <cuda_runtime.h>

#define SEQ    4096
#define BATCH  16
#define HIDDEN 512
#define SPC    16                    // s per chunk
#define CPB    (SEQ / SPC)           // 256 chunks per batch
#define SLOTS  37                    // persistent slots per batch
#define CTXN   (BATCH * HIDDEN)      // 8192

// Scratch (no allocations allowed) — all fully re-written every launch.
__device__ float g_dec[BATCH * HIDDEN];              // decoder features [b][h]
__device__ float g_w[BATCH * SEQ];                   // unnormalized masked weights
__device__ float g_zpart[BATCH * SLOTS];             // per-(b,slot) Z partials
__device__ float g_part[BATCH * SLOTS * HIDDEN];     // ctx partials [b][slot][h]

__device__ __forceinline__ float tanh_fast(float x) {
    float y;
    asm("tanh.approx.f32 %0, %1;" : "=f"(y) : "f"(x));
    return y;
}

__device__ __forceinline__ void pdl_wait() {
    asm volatile("griddepcontrol.wait;" ::: "memory");
}
__device__ __forceinline__ void pdl_launch_dependents() {
    asm volatile("griddepcontrol.launch_dependents;" ::: "memory");
}

// ---------------------------------------------------------------------------
// K0: decoder_features[b,k] = dot(x[b,:], W[k,:]) + bias[k].
// Grid 256 = 16 b * 16 k-groups of 32. Block 256 (8 warps), FOUR rows per warp
// (16 W LDG.128 per thread in flight). Small footprint so kmain blocks can
// co-reside under PDL and prefetch encf while k0 runs.
// ---------------------------------------------------------------------------
__global__ void k0_dec(const float* __restrict__ x, const float* __restrict__ W,
                       const float* __restrict__ bias) {
    pdl_launch_dependents();     // let kmain pre-launch; it gates on pdl_wait()

    int b    = blockIdx.x >> 4;
    int kg   = blockIdx.x & 15;
    int tid  = threadIdx.x;               // 256
    int warp = tid >> 5, lane = tid & 31;
    int k0 = kg * 32 + warp * 4;

    const float4* xr = reinterpret_cast<const float4*>(x + (size_t)b * HIDDEN);
    float4 xv[4];
#pragma unroll
    for (int j = 0; j < 4; ++j) xv[j] = __ldg(&xr[lane + j * 32]);

    float4 wv[4][4];
#pragma unroll
    for (int r = 0; r < 4; ++r) {
        const float4* Wr = reinterpret_cast<const float4*>(W + (size_t)(k0 + r) * HIDDEN);
#pragma unroll
        for (int j = 0; j < 4; ++j) wv[r][j] = Wr[lane + j * 32];
    }

    float acc[4] = {0.f, 0.f, 0.f, 0.f};
#pragma unroll
    for (int r = 0; r < 4; ++r)
#pragma unroll
        for (int j = 0; j < 4; ++j)
            acc[r] += wv[r][j].x * xv[j].x + wv[r][j].y * xv[j].y
                    + wv[r][j].z * xv[j].z + wv[r][j].w * xv[j].w;

#pragma unroll
    for (int r = 0; r < 4; ++r) {
#pragma unroll
        for (int off = 16; off; off >>= 1)
            acc[r] += __shfl_down_sync(0xffffffffu, acc[r], off);
        if (lane == 0) g_dec[b * HIDDEN + k0 + r] = acc[r] + bias[k0 + r];
    }
}

// ---------------------------------------------------------------------------
// KMAIN: persistent fused scores+context — proven round-11 body, with the
// FIRST chunk's encf loads peeled ABOVE pdl_wait() so they stream while k0
// executes. Grid 592 = 16 b * 37 slots, block 256 (8 warps).
// ---------------------------------------------------------------------------
__global__ void __launch_bounds__(256, 5)
kmain(const float* __restrict__ encf, const float* __restrict__ enc,
      const float* __restrict__ mask, const float* __restrict__ tss,
      const float* __restrict__ v,    float* __restrict__ out_newsum) {
    int b    = blockIdx.x / SLOTS;
    int slot = blockIdx.x % SLOTS;
    int tid  = threadIdx.x;               // 256
    int warp = tid >> 5, lane = tid & 31;

    __shared__ float4 ds_s[HIDDEN / 4];   // 128 float4
    __shared__ float4 vs_s[HIDDEN / 4];
    __shared__ float4 red_s[HIDDEN / 4];  // parity-reduce staging
    __shared__ float  ws[SPC];
    __shared__ float  zs[8];

    // ---- k0-independent prologue (overlaps k0 under PDL) ----
    if (tid >= 128) vs_s[tid - 128] = reinterpret_cast<const float4*>(v)[tid - 128];

    // Prefetch FIRST chunk's encf rows (depends only on inputs).
    float4 ev[2][4];
    {
        int s0 = slot * SPC + warp * 2;
#pragma unroll
        for (int i = 0; i < 2; ++i) {
            const float4* row =
                reinterpret_cast<const float4*>(encf + ((size_t)(s0 + i) * BATCH + b) * HIDDEN);
#pragma unroll
            for (int j = 0; j < 4; ++j) ev[i][j] = row[lane + j * 32];
        }
    }

    pdl_wait();                           // k0's g_dec now visible
    if (tid < 128) ds_s[tid] = reinterpret_cast<const float4*>(g_dec + b * HIDDEN)[tid];
    pdl_launch_dependents();              // let k4 pre-launch; it gates on pdl_wait()
    __syncthreads();

    // Phase-B persistent state.
    int par = tid >> 7;                   // 0/1
    int h4  = tid & 127;
    const size_t strideS = (size_t)BATCH * (HIDDEN / 4);     // float4s per s-step
    const float4* enc4 = reinterpret_cast<const float4*>(enc);
    float4 ctx = make_float4(0.f, 0.f, 0.f, 0.f);
    float zacc = 0.0f;

    for (int c = slot; c < CPB; c += SLOTS) {
        int sbase = c * SPC;
        int s0 = sbase + warp * 2;

        // ---- Phase A: 2 rows per warp (first chunk's ev already loaded) ----
        if (c != slot) {
#pragma unroll
            for (int i = 0; i < 2; ++i) {
                const float4* row =
                    reinterpret_cast<const float4*>(encf + ((size_t)(s0 + i) * BATCH + b) * HIDDEN);
#pragma unroll
                for (int j = 0; j < 4; ++j) ev[i][j] = row[lane + j * 32];
            }
        }
        float acc[2] = {0.f, 0.f};
#pragma unroll
        for (int j = 0; j < 4; ++j) {
            float4 d4 = ds_s[lane + j * 32];     // LDS.128, conflict-free
            float4 v4 = vs_s[lane + j * 32];
#pragma unroll
            for (int i = 0; i < 2; ++i) {
                acc[i] += tanh_fast(d4.x + ev[i][j].x) * v4.x;
                acc[i] += tanh_fast(d4.y + ev[i][j].y) * v4.y;
                acc[i] += tanh_fast(d4.z + ev[i][j].z) * v4.z;
                acc[i] += tanh_fast(d4.w + ev[i][j].w) * v4.w;
            }
        }
#pragma unroll
        for (int i = 0; i < 2; ++i) {
#pragma unroll
            for (int off = 16; off; off >>= 1)
                acc[i] += __shfl_down_sync(0xffffffffu, acc[i], off);
            if (lane == 0) {
                int s = s0 + i;
                float e = expf(acc[i]);
                float t = tss[b * SEQ + s];
                float w = mask[b * SEQ + s] * e / t;
                out_newsum[b * SEQ + s] = e + t;
                g_w[b * SEQ + s] = w;
                ws[warp * 2 + i] = w;
                zacc += w;
            }
        }
        __syncthreads();

        // ---- Phase B: accumulate ctx for this chunk ----
        const float4* p = enc4 + ((size_t)(sbase + par) * BATCH + b) * (HIDDEN / 4) + h4;
#pragma unroll
        for (int i = 0; i < SPC / 2; ++i) {
            float  wv = ws[2 * i + par];
            float4 e  = __ldg(p + (size_t)(2 * i) * strideS);
            ctx.x += wv * e.x; ctx.y += wv * e.y; ctx.z += wv * e.z; ctx.w += wv * e.w;
        }
        __syncthreads();   // keep warps phase-aligned (proven necessary in R9)
    }

    // ---- Parity reduce: one ctx partial per (b,slot,h) ----
    if (par == 1) red_s[h4] = ctx;
    __syncthreads();
    if (par == 0) {
        float4 o = red_s[h4];
        ctx.x += o.x; ctx.y += o.y; ctx.z += o.z; ctx.w += o.w;
        reinterpret_cast<float4*>(g_part)
            [((size_t)b * SLOTS + slot) * (HIDDEN / 4) + h4] = ctx;
    }

    // Deterministic Z partial for this (b, slot).
    if (lane == 0) zs[warp] = zacc;
    __syncthreads();
    if (tid == 0) {
        float z = 0.0f;
#pragma unroll
        for (int i = 0; i < 8; ++i) z += zs[i];
        g_zpart[b * SLOTS + slot] = z;
    }
}

// ---------------------------------------------------------------------------
// K4 (fused epilogue): blocks 0..31: ctx = (sum of 37 partials)/Z -> out[0:8192)
//                      blocks 32..287: attention = w/Z -> out[8192:73728)
// ---------------------------------------------------------------------------
__global__ void k4_final(float* __restrict__ out) {
    pdl_wait();                           // kmain's g_part/g_zpart/g_w visible

    int bid = blockIdx.x, tid = threadIdx.x;
    if (bid < 32) {
        int i = bid * 256 + tid;            // 0..8191
        int b = i >> 9;
        float Z = 0.0f;
#pragma unroll
        for (int j = 0; j < SLOTS; ++j) Z += g_zpart[b * SLOTS + j];
        float acc = 0.0f;
        int h = i & (HIDDEN - 1);
#pragma unroll
        for (int p = 0; p < SLOTS; ++p)
            acc += g_part[((size_t)b * SLOTS + p) * HIDDEN + h];
        out[i] = acc / Z;
    } else {
        int i = (bid - 32) * 256 + tid;     // 0..65535
        int b = i >> 12;
        float Z = 0.0f;
#pragma unroll
        for (int j = 0; j < SLOTS; ++j) Z += g_zpart[b * SLOTS + j];
        out[CTXN + i] = g_w[i] / Z;
    }
}

// ---------------------------------------------------------------------------
extern "C" void kernel_launch(void* const* d_in, const int* in_sizes, int n_in,
                              void* d_out, int out_size) {
    const float* x    = (const float*)d_in[0];  // outputs_hidden [1,16,512]
    const float* enc  = (const float*)d_in[1];  // encoder_out [4096,16,512]
    const float* encf = (const float*)d_in[2];  // encoder_features [4096,16,512]
    const float* mask = (const float*)d_in[3];  // encoder_mask [16,1,4096]
    const float* tss  = (const float*)d_in[4];  // temporal_scores_sum [16,1,4096]
    const float* W    = (const float*)d_in[5];  // W_feat [512,512]
    const float* bias = (const float*)d_in[6];  // b_feat [512]
    const float* v    = (const float*)d_in[7];  // v_attn [512]

    float* out        = (float*)d_out;
    float* out_newsum = out + CTXN + BATCH * SEQ;  // third output

    k0_dec<<<256, 256>>>(x, W, bias);

    // kmain with programmatic dependent launch (overlaps k0 with encf prefetch).
    {
        cudaLaunchAttribute attr[1];
        attr[0].id = cudaLaunchAttributeProgrammaticStreamSerialization;
        attr[0].val.programmaticStreamSerializationAllowed = 1;
        cudaLaunchConfig_t cfg = {};
        cfg.gridDim  = dim3(BATCH * SLOTS, 1, 1);
        cfg.blockDim = dim3(256, 1, 1);
        cfg.attrs    = attr;
        cfg.numAttrs = 1;
        cudaLaunchKernelEx(&cfg, kmain, encf, enc, mask, tss, v, out_newsum);
    }

    // k4 with PDL (overlaps kmain's tail/launch).
    {
        cudaLaunchAttribute attr[1];
        attr[0].id = cudaLaunchAttributeProgrammaticStreamSerialization;
        attr[0].val.programmaticStreamSerializationAllowed = 1;
        cudaLaunchConfig_t cfg = {};
        cfg.gridDim  = dim3(288, 1, 1);
        cfg.blockDim = dim3(256, 1, 1);
        cfg.attrs    = attr;
        cfg.numAttrs = 1;
        cudaLaunchKernelEx(&cfg, k4_final, out);
    }
}

// round 14
// speedup vs baseline: 1.1572x; 1.1572x over previous
#include <cuda_runtime.h>

#define SEQ    4096
#define BATCH  16
#define HIDDEN 512
#define SPC    16                    // s per chunk
#define CPB    (SEQ / SPC)           // 256 chunks per batch
#define SLOTS  37                    // persistent slots per batch
#define CTXN   (BATCH * HIDDEN)      // 8192

// Scratch (no allocations allowed) — all fully re-written every launch.
__device__ float g_dec[BATCH * HIDDEN];              // decoder features [b][h]
__device__ float g_w[BATCH * SEQ];                   // unnormalized masked weights
__device__ float g_zpart[BATCH * SLOTS];             // per-(b,slot) Z partials
__device__ float g_part[BATCH * SLOTS * HIDDEN];     // ctx partials [b][slot][h]

__device__ __forceinline__ float tanh_fast(float x) {
    float y;
    asm("tanh.approx.f32 %0, %1;" : "=f"(y) : "f"(x));
    return y;
}

__device__ __forceinline__ void pdl_wait() {
    asm volatile("griddepcontrol.wait;" ::: "memory");
}
__device__ __forceinline__ void pdl_launch_dependents() {
    asm volatile("griddepcontrol.launch_dependents;" ::: "memory");
}

// ---------------------------------------------------------------------------
// K0: decoder_features[b,k] = dot(x[b,:], W[k,:]) + bias[k].
// Grid 512 = 16 b * 32 k-groups of 16 (measured-best config). Block 256,
// TWO rows per warp.
// ---------------------------------------------------------------------------
__global__ void k0_dec(const float* __restrict__ x, const float* __restrict__ W,
                       const float* __restrict__ bias) {
    pdl_launch_dependents();     // let kmain pre-launch; it gates on pdl_wait()

    int b    = blockIdx.x >> 5;
    int kg   = blockIdx.x & 31;
    int tid  = threadIdx.x;               // 256
    int warp = tid >> 5, lane = tid & 31;
    int k0 = kg * 16 + warp * 2;

    const float4* xr = reinterpret_cast<const float4*>(x + (size_t)b * HIDDEN);
    float4 xv[4];
#pragma unroll
    for (int j = 0; j < 4; ++j) xv[j] = __ldg(&xr[lane + j * 32]);

    float4 wv[2][4];
#pragma unroll
    for (int r = 0; r < 2; ++r) {
        const float4* Wr = reinterpret_cast<const float4*>(W + (size_t)(k0 + r) * HIDDEN);
#pragma unroll
        for (int j = 0; j < 4; ++j) wv[r][j] = Wr[lane + j * 32];
    }

    float acc[2] = {0.f, 0.f};
#pragma unroll
    for (int r = 0; r < 2; ++r)
#pragma unroll
        for (int j = 0; j < 4; ++j)
            acc[r] += wv[r][j].x * xv[j].x + wv[r][j].y * xv[j].y
                    + wv[r][j].z * xv[j].z + wv[r][j].w * xv[j].w;

#pragma unroll
    for (int r = 0; r < 2; ++r) {
#pragma unroll
        for (int off = 16; off; off >>= 1)
            acc[r] += __shfl_down_sync(0xffffffffu, acc[r], off);
        if (lane == 0) g_dec[b * HIDDEN + k0 + r] = acc[r] + bias[k0 + r];
    }
}

// ---------------------------------------------------------------------------
// KMAIN: persistent fused scores+context. FIRST chunk fully peeled into the
// prologue (its encf loads issue BEFORE pdl_wait, overlapping k0); the main
// loop is the byte-identical round-11 body with no extra branches.
// Grid 592 = 16 b * 37 slots, block 256 (8 warps).
// ---------------------------------------------------------------------------
__global__ void __launch_bounds__(256, 5)
kmain(const float* __restrict__ encf, const float* __restrict__ enc,
      const float* __restrict__ mask, const float* __restrict__ tss,
      const float* __restrict__ v,    float* __restrict__ out_newsum) {
    int b    = blockIdx.x / SLOTS;
    int slot = blockIdx.x % SLOTS;
    int tid  = threadIdx.x;               // 256
    int warp = tid >> 5, lane = tid & 31;

    __shared__ float4 ds_s[HIDDEN / 4];   // 128 float4
    __shared__ float4 vs_s[HIDDEN / 4];
    __shared__ float4 red_s[HIDDEN / 4];  // parity-reduce staging
    __shared__ float  ws[SPC];
    __shared__ float  zs[8];

    // Phase-B persistent state.
    int par = tid >> 7;                   // 0/1
    int h4  = tid & 127;
    const size_t strideS = (size_t)BATCH * (HIDDEN / 4);     // float4s per s-step
    const float4* enc4 = reinterpret_cast<const float4*>(enc);
    float4 ctx = make_float4(0.f, 0.f, 0.f, 0.f);
    float zacc = 0.0f;

    // ====================== PEELED FIRST CHUNK ======================
    {
        int sbase = slot * SPC;
        int s0 = sbase + warp * 2;

        // k0-independent: stage v + load first chunk's encf (overlaps k0).
        if (tid >= 128) vs_s[tid - 128] = reinterpret_cast<const float4*>(v)[tid - 128];
        float4 ev[2][4];
#pragma unroll
        for (int i = 0; i < 2; ++i) {
            const float4* row =
                reinterpret_cast<const float4*>(encf + ((size_t)(s0 + i) * BATCH + b) * HIDDEN);
#pragma unroll
            for (int j = 0; j < 4; ++j) ev[i][j] = row[lane + j * 32];
        }

        pdl_wait();                       // k0's g_dec now visible
        if (tid < 128) ds_s[tid] = reinterpret_cast<const float4*>(g_dec + b * HIDDEN)[tid];
        pdl_launch_dependents();          // let k4 pre-launch; it gates on pdl_wait()
        __syncthreads();

        float acc[2] = {0.f, 0.f};
#pragma unroll
        for (int j = 0; j < 4; ++j) {
            float4 d4 = ds_s[lane + j * 32];
            float4 v4 = vs_s[lane + j * 32];
#pragma unroll
            for (int i = 0; i < 2; ++i) {
                acc[i] += tanh_fast(d4.x + ev[i][j].x) * v4.x;
                acc[i] += tanh_fast(d4.y + ev[i][j].y) * v4.y;
                acc[i] += tanh_fast(d4.z + ev[i][j].z) * v4.z;
                acc[i] += tanh_fast(d4.w + ev[i][j].w) * v4.w;
            }
        }
#pragma unroll
        for (int i = 0; i < 2; ++i) {
#pragma unroll
            for (int off = 16; off; off >>= 1)
                acc[i] += __shfl_down_sync(0xffffffffu, acc[i], off);
            if (lane == 0) {
                int s = s0 + i;
                float e = expf(acc[i]);
                float t = tss[b * SEQ + s];
                float w = mask[b * SEQ + s] * e / t;
                out_newsum[b * SEQ + s] = e + t;
                g_w[b * SEQ + s] = w;
                ws[warp * 2 + i] = w;
                zacc += w;
            }
        }
        __syncthreads();

        const float4* p = enc4 + ((size_t)(sbase + par) * BATCH + b) * (HIDDEN / 4) + h4;
#pragma unroll
        for (int i = 0; i < SPC / 2; ++i) {
            float  wv = ws[2 * i + par];
            float4 e  = __ldg(p + (size_t)(2 * i) * strideS);
            ctx.x += wv * e.x; ctx.y += wv * e.y; ctx.z += wv * e.z; ctx.w += wv * e.w;
        }
        __syncthreads();
    }

    // ====================== MAIN LOOP (round-11 body, untouched) ======================
    for (int c = slot + SLOTS; c < CPB; c += SLOTS) {
        int sbase = c * SPC;
        int s0 = sbase + warp * 2;

        // ---- Phase A: 2 rows per warp ----
        float4 ev[2][4];
#pragma unroll
        for (int i = 0; i < 2; ++i) {
            const float4* row =
                reinterpret_cast<const float4*>(encf + ((size_t)(s0 + i) * BATCH + b) * HIDDEN);
#pragma unroll
            for (int j = 0; j < 4; ++j) ev[i][j] = row[lane + j * 32];
        }
        float acc[2] = {0.f, 0.f};
#pragma unroll
        for (int j = 0; j < 4; ++j) {
            float4 d4 = ds_s[lane + j * 32];     // LDS.128, conflict-free
            float4 v4 = vs_s[lane + j * 32];
#pragma unroll
            for (int i = 0; i < 2; ++i) {
                acc[i] += tanh_fast(d4.x + ev[i][j].x) * v4.x;
                acc[i] += tanh_fast(d4.y + ev[i][j].y) * v4.y;
                acc[i] += tanh_fast(d4.z + ev[i][j].z) * v4.z;
                acc[i] += tanh_fast(d4.w + ev[i][j].w) * v4.w;
            }
        }
#pragma unroll
        for (int i = 0; i < 2; ++i) {
#pragma unroll
            for (int off = 16; off; off >>= 1)
                acc[i] += __shfl_down_sync(0xffffffffu, acc[i], off);
            if (lane == 0) {
                int s = s0 + i;
                float e = expf(acc[i]);
                float t = tss[b * SEQ + s];
                float w = mask[b * SEQ + s] * e / t;
                out_newsum[b * SEQ + s] = e + t;
                g_w[b * SEQ + s] = w;
                ws[warp * 2 + i] = w;
                zacc += w;
            }
        }
        __syncthreads();

        // ---- Phase B: accumulate ctx for this chunk ----
        const float4* p = enc4 + ((size_t)(sbase + par) * BATCH + b) * (HIDDEN / 4) + h4;
#pragma unroll
        for (int i = 0; i < SPC / 2; ++i) {
            float  wv = ws[2 * i + par];
            float4 e  = __ldg(p + (size_t)(2 * i) * strideS);
            ctx.x += wv * e.x; ctx.y += wv * e.y; ctx.z += wv * e.z; ctx.w += wv * e.w;
        }
        __syncthreads();   // keep warps phase-aligned (proven necessary in R9)
    }

    // ---- Parity reduce: one ctx partial per (b,slot,h) ----
    if (par == 1) red_s[h4] = ctx;
    __syncthreads();
    if (par == 0) {
        float4 o = red_s[h4];
        ctx.x += o.x; ctx.y += o.y; ctx.z += o.z; ctx.w += o.w;
        reinterpret_cast<float4*>(g_part)
            [((size_t)b * SLOTS + slot) * (HIDDEN / 4) + h4] = ctx;
    }

    // Deterministic Z partial for this (b, slot).
    if (lane == 0) zs[warp] = zacc;
    __syncthreads();
    if (tid == 0) {
        float z = 0.0f;
#pragma unroll
        for (int i = 0; i < 8; ++i) z += zs[i];
        g_zpart[b * SLOTS + slot] = z;
    }
}

// ---------------------------------------------------------------------------
// K4 (fused epilogue): blocks 0..31: ctx = (sum of 37 partials)/Z -> out[0:8192)
//                      blocks 32..287: attention = w/Z -> out[8192:73728)
// ---------------------------------------------------------------------------
__global__ void k4_final(float* __restrict__ out) {
    pdl_wait();                           // kmain's g_part/g_zpart/g_w visible

    int bid = blockIdx.x, tid = threadIdx.x;
    if (bid < 32) {
        int i = bid * 256 + tid;            // 0..8191
        int b = i >> 9;
        float Z = 0.0f;
#pragma unroll
        for (int j = 0; j < SLOTS; ++j) Z += g_zpart[b * SLOTS + j];
        float acc = 0.0f;
        int h = i & (HIDDEN - 1);
#pragma unroll
        for (int p = 0; p < SLOTS; ++p)
            acc += g_part[((size_t)b * SLOTS + p) * HIDDEN + h];
        out[i] = acc / Z;
    } else {
        int i = (bid - 32) * 256 + tid;     // 0..65535
        int b = i >> 12;
        float Z = 0.0f;
#pragma unroll
        for (int j = 0; j < SLOTS; ++j) Z += g_zpart[b * SLOTS + j];
        out[CTXN + i] = g_w[i] / Z;
    }
}

// ---------------------------------------------------------------------------
extern "C" void kernel_launch(void* const* d_in, const int* in_sizes, int n_in,
                              void* d_out, int out_size) {
    const float* x    = (const float*)d_in[0];  // outputs_hidden [1,16,512]
    const float* enc  = (const float*)d_in[1];  // encoder_out [4096,16,512]
    const float* encf = (const float*)d_in[2];  // encoder_features [4096,16,512]
    const float* mask = (const float*)d_in[3];  // encoder_mask [16,1,4096]
    const float* tss  = (const float*)d_in[4];  // temporal_scores_sum [16,1,4096]
    const float* W    = (const float*)d_in[5];  // W_feat [512,512]
    const float* bias = (const float*)d_in[6];  // b_feat [512]
    const float* v    = (const float*)d_in[7];  // v_attn [512]

    float* out        = (float*)d_out;
    float* out_newsum = out + CTXN + BATCH * SEQ;  // third output

    k0_dec<<<512, 256>>>(x, W, bias);

    // kmain with PDL (first-chunk encf loads overlap k0).
    {
        cudaLaunchAttribute attr[1];
        attr[0].id = cudaLaunchAttributeProgrammaticStreamSerialization;
        attr[0].val.programmaticStreamSerializationAllowed = 1;
        cudaLaunchConfig_t cfg = {};
        cfg.gridDim  = dim3(BATCH * SLOTS, 1, 1);
        cfg.blockDim = dim3(256, 1, 1);
        cfg.attrs    = attr;
        cfg.numAttrs = 1;
        cudaLaunchKernelEx(&cfg, kmain, encf, enc, mask, tss, v, out_newsum);
    }

    // k4 with PDL (overlaps kmain's tail/launch).
    {
        cudaLaunchAttribute attr[1];
        attr[0].id = cudaLaunchAttributeProgrammaticStreamSerialization;
        attr[0].val.programmaticStreamSerializationAllowed = 1;
        cudaLaunchConfig_t cfg = {};
        cfg.gridDim  = dim3(288, 1, 1);
        cfg.blockDim = dim3(256, 1, 1);
        cfg.attrs    = attr;
        cfg.numAttrs = 1;
        cudaLaunchKernelEx(&cfg, k4_final, out);
    }
}

// round 15
// speedup vs baseline: 1.1663x; 1.0078x over previous
#include <cuda_runtime.h>

#define SEQ    4096
#define BATCH  16
#define HIDDEN 512
#define SPC    16                    // s per chunk
#define CPB    (SEQ / SPC)           // 256 chunks per batch
#define SLOTS  46                    // persistent slots per batch (736 blocks = ~5/SM)
#define CTXN   (BATCH * HIDDEN)      // 8192

// Scratch (no allocations allowed) — all fully re-written every launch.
__device__ float g_dec[BATCH * HIDDEN];              // decoder features [b][h]
__device__ float g_w[BATCH * SEQ];                   // unnormalized masked weights
__device__ float g_zpart[BATCH * SLOTS];             // per-(b,slot) Z partials
__device__ float g_part[BATCH * SLOTS * HIDDEN];     // ctx partials [b][slot][h]

__device__ __forceinline__ float tanh_fast(float x) {
    float y;
    asm("tanh.approx.f32 %0, %1;" : "=f"(y) : "f"(x));
    return y;
}

// ---------------------------------------------------------------------------
// K0: decoder_features[b,k] = dot(x[b,:], W[k,:]) + bias[k].
// Grid 512 = 16 b * 32 k-groups of 16 (measured-best). Block 256, 2 rows/warp.
// ---------------------------------------------------------------------------
__global__ void k0_dec(const float* __restrict__ x, const float* __restrict__ W,
                       const float* __restrict__ bias) {
    int b    = blockIdx.x >> 5;
    int kg   = blockIdx.x & 31;
    int tid  = threadIdx.x;               // 256
    int warp = tid >> 5, lane = tid & 31;
    int k0 = kg * 16 + warp * 2;

    const float4* xr = reinterpret_cast<const float4*>(x + (size_t)b * HIDDEN);
    float4 xv[4];
#pragma unroll
    for (int j = 0; j < 4; ++j) xv[j] = __ldg(&xr[lane + j * 32]);

    float4 wv[2][4];
#pragma unroll
    for (int r = 0; r < 2; ++r) {
        const float4* Wr = reinterpret_cast<const float4*>(W + (size_t)(k0 + r) * HIDDEN);
#pragma unroll
        for (int j = 0; j < 4; ++j) wv[r][j] = Wr[lane + j * 32];
    }

    float acc[2] = {0.f, 0.f};
#pragma unroll
    for (int r = 0; r < 2; ++r)
#pragma unroll
        for (int j = 0; j < 4; ++j)
            acc[r] += wv[r][j].x * xv[j].x + wv[r][j].y * xv[j].y
                    + wv[r][j].z * xv[j].z + wv[r][j].w * xv[j].w;

#pragma unroll
    for (int r = 0; r < 2; ++r) {
#pragma unroll
        for (int off = 16; off; off >>= 1)
            acc[r] += __shfl_down_sync(0xffffffffu, acc[r], off);
        if (lane == 0) g_dec[b * HIDDEN + k0 + r] = acc[r] + bias[k0 + r];
    }
}

// ---------------------------------------------------------------------------
// KMAIN: persistent fused scores+context — round-11 champion body, with
// SLOTS=46 so the grid (736) actually fills 5 blocks/SM (40 warps).
// ---------------------------------------------------------------------------
__global__ void __launch_bounds__(256, 5)
kmain(const float* __restrict__ encf, const float* __restrict__ enc,
      const float* __restrict__ mask, const float* __restrict__ tss,
      const float* __restrict__ v,    float* __restrict__ out_newsum) {
    int b    = blockIdx.x / SLOTS;
    int slot = blockIdx.x % SLOTS;
    int tid  = threadIdx.x;               // 256
    int warp = tid >> 5, lane = tid & 31;

    __shared__ float4 ds_s[HIDDEN / 4];   // 128 float4
    __shared__ float4 vs_s[HIDDEN / 4];
    __shared__ float4 red_s[HIDDEN / 4];  // parity-reduce staging
    __shared__ float  ws[SPC];
    __shared__ float  zs[8];

    // Stage decoder features + v into shared (once per block).
    if (tid < 128) ds_s[tid] = reinterpret_cast<const float4*>(g_dec + b * HIDDEN)[tid];
    else           vs_s[tid - 128] = reinterpret_cast<const float4*>(v)[tid - 128];
    __syncthreads();

    // Phase-B persistent state.
    int par = tid >> 7;                   // 0/1
    int h4  = tid & 127;
    const size_t strideS = (size_t)BATCH * (HIDDEN / 4);     // float4s per s-step
    const float4* enc4 = reinterpret_cast<const float4*>(enc);
    float4 ctx = make_float4(0.f, 0.f, 0.f, 0.f);
    float zacc = 0.0f;

    for (int c = slot; c < CPB; c += SLOTS) {
        int sbase = c * SPC;
        int s0 = sbase + warp * 2;

        // ---- Phase A: 2 rows per warp ----
        float4 ev[2][4];
#pragma unroll
        for (int i = 0; i < 2; ++i) {
            const float4* row =
                reinterpret_cast<const float4*>(encf + ((size_t)(s0 + i) * BATCH + b) * HIDDEN);
#pragma unroll
            for (int j = 0; j < 4; ++j) ev[i][j] = row[lane + j * 32];
        }
        float acc[2] = {0.f, 0.f};
#pragma unroll
        for (int j = 0; j < 4; ++j) {
            float4 d4 = ds_s[lane + j * 32];     // LDS.128, conflict-free
            float4 v4 = vs_s[lane + j * 32];
#pragma unroll
            for (int i = 0; i < 2; ++i) {
                acc[i] += tanh_fast(d4.x + ev[i][j].x) * v4.x;
                acc[i] += tanh_fast(d4.y + ev[i][j].y) * v4.y;
                acc[i] += tanh_fast(d4.z + ev[i][j].z) * v4.z;
                acc[i] += tanh_fast(d4.w + ev[i][j].w) * v4.w;
            }
        }
#pragma unroll
        for (int i = 0; i < 2; ++i) {
#pragma unroll
            for (int off = 16; off; off >>= 1)
                acc[i] += __shfl_down_sync(0xffffffffu, acc[i], off);
            if (lane == 0) {
                int s = s0 + i;
                float e = expf(acc[i]);
                float t = tss[b * SEQ + s];
                float w = mask[b * SEQ + s] * e / t;
                out_newsum[b * SEQ + s] = e + t;
                g_w[b * SEQ + s] = w;
                ws[warp * 2 + i] = w;
                zacc += w;
            }
        }
        __syncthreads();

        // ---- Phase B: accumulate ctx for this chunk ----
        const float4* p = enc4 + ((size_t)(sbase + par) * BATCH + b) * (HIDDEN / 4) + h4;
#pragma unroll
        for (int i = 0; i < SPC / 2; ++i) {
            float  wv = ws[2 * i + par];
            float4 e  = __ldg(p + (size_t)(2 * i) * strideS);
            ctx.x += wv * e.x; ctx.y += wv * e.y; ctx.z += wv * e.z; ctx.w += wv * e.w;
        }
        __syncthreads();   // keep warps phase-aligned (proven necessary in R9)
    }

    // ---- Parity reduce: one ctx partial per (b,slot,h) ----
    if (par == 1) red_s[h4] = ctx;
    __syncthreads();
    if (par == 0) {
        float4 o = red_s[h4];
        ctx.x += o.x; ctx.y += o.y; ctx.z += o.z; ctx.w += o.w;
        reinterpret_cast<float4*>(g_part)
            [((size_t)b * SLOTS + slot) * (HIDDEN / 4) + h4] = ctx;
    }

    // Deterministic Z partial for this (b, slot).
    if (lane == 0) zs[warp] = zacc;
    __syncthreads();
    if (tid == 0) {
        float z = 0.0f;
#pragma unroll
        for (int i = 0; i < 8; ++i) z += zs[i];
        g_zpart[b * SLOTS + slot] = z;
    }
}

// ---------------------------------------------------------------------------
// K4 (fused epilogue): blocks 0..31: ctx = (sum of 46 partials)/Z -> out[0:8192)
//                      blocks 32..287: attention = w/Z -> out[8192:73728)
// ---------------------------------------------------------------------------
__global__ void k4_final(float* __restrict__ out) {
    int bid = blockIdx.x, tid = threadIdx.x;
    if (bid < 32) {
        int i = bid * 256 + tid;            // 0..8191
        int b = i >> 9;
        float Z = 0.0f;
#pragma unroll
        for (int j = 0; j < SLOTS; ++j) Z += g_zpart[b * SLOTS + j];
        float acc = 0.0f;
        int h = i & (HIDDEN - 1);
#pragma unroll
        for (int p = 0; p < SLOTS; ++p)
            acc += g_part[((size_t)b * SLOTS + p) * HIDDEN + h];
        out[i] = acc / Z;
    } else {
        int i = (bid - 32) * 256 + tid;     // 0..65535
        int b = i >> 12;
        float Z = 0.0f;
#pragma unroll
        for (int j = 0; j < SLOTS; ++j) Z += g_zpart[b * SLOTS + j];
        out[CTXN + i] = g_w[i] / Z;
    }
}

// ---------------------------------------------------------------------------
extern "C" void kernel_launch(void* const* d_in, const int* in_sizes, int n_in,
                              void* d_out, int out_size) {
    const float* x    = (const float*)d_in[0];  // outputs_hidden [1,16,512]
    const float* enc  = (const float*)d_in[1];  // encoder_out [4096,16,512]
    const float* encf = (const float*)d_in[2];  // encoder_features [4096,16,512]
    const float* mask = (const float*)d_in[3];  // encoder_mask [16,1,4096]
    const float* tss  = (const float*)d_in[4];  // temporal_scores_sum [16,1,4096]
    const float* W    = (const float*)d_in[5];  // W_feat [512,512]
    const float* bias = (const float*)d_in[6];  // b_feat [512]
    const float* v    = (const float*)d_in[7];  // v_attn [512]

    float* out        = (float*)d_out;
    float* out_newsum = out + CTXN + BATCH * SEQ;  // third output

    k0_dec  <<<512,           256>>>(x, W, bias);
    kmain   <<<BATCH * SLOTS, 256>>>(encf, enc, mask, tss, v, out_newsum);
    k4_final<<<288,           256>>>(out);
}